// round 2
// baseline (speedup 1.0000x reference)
#include <cuda_runtime.h>
#include <math.h>

#define D_MODEL 1024
#define NHEAD   16
#define DHEAD   64
#define BB      2
#define TT      2048
#define SSEQ    2048
#define MROWS   (BB*TT)      // 4096
#define DFF_    4096

// ---------------- scratch (device globals; no runtime allocation) ----------------
__device__ float g_q  [MROWS * D_MODEL];
__device__ float g_k  [MROWS * D_MODEL];
__device__ float g_v  [MROWS * D_MODEL];
__device__ float g_ctx[MROWS * D_MODEL];
__device__ float g_tmp[MROWS * D_MODEL];
__device__ float g_x1 [MROWS * D_MODEL];
__device__ float g_x2 [MROWS * D_MODEL];
__device__ float g_ffh[(size_t)MROWS * DFF_];

// ---------------- SGEMM: C = A(MxK) @ B(NxK)^T + bias [+resid] [relu] ----------------
// 128x128 tile, BK=16, 256 threads, 8x8 per thread.
__global__ __launch_bounds__(256) void sgemm_nt(
    const float* __restrict__ A, const float* __restrict__ B,
    const float* __restrict__ bias, const float* __restrict__ resid,
    float* __restrict__ C, int M, int N, int K, int do_relu)
{
    __shared__ float As[16][128];
    __shared__ float Bs[16][128];
    const int tid = threadIdx.x;
    const int tx = tid & 15;
    const int ty = tid >> 4;
    const int bm = blockIdx.y * 128;
    const int bn = blockIdx.x * 128;

    float acc[8][8];
#pragma unroll
    for (int i = 0; i < 8; i++)
#pragma unroll
        for (int j = 0; j < 8; j++) acc[i][j] = 0.f;

    const int lrow = tid >> 2;   // 0..63
    const int lkq  = tid & 3;    // float4 index within 16-wide k slab

    for (int k0 = 0; k0 < K; k0 += 16) {
        float4 a0 = *(const float4*)(A + (size_t)(bm + lrow)      * K + k0 + lkq * 4);
        float4 a1 = *(const float4*)(A + (size_t)(bm + lrow + 64) * K + k0 + lkq * 4);
        float4 b0 = *(const float4*)(B + (size_t)(bn + lrow)      * K + k0 + lkq * 4);
        float4 b1 = *(const float4*)(B + (size_t)(bn + lrow + 64) * K + k0 + lkq * 4);
        __syncthreads();
        As[lkq*4+0][lrow] = a0.x; As[lkq*4+1][lrow] = a0.y;
        As[lkq*4+2][lrow] = a0.z; As[lkq*4+3][lrow] = a0.w;
        As[lkq*4+0][lrow+64] = a1.x; As[lkq*4+1][lrow+64] = a1.y;
        As[lkq*4+2][lrow+64] = a1.z; As[lkq*4+3][lrow+64] = a1.w;
        Bs[lkq*4+0][lrow] = b0.x; Bs[lkq*4+1][lrow] = b0.y;
        Bs[lkq*4+2][lrow] = b0.z; Bs[lkq*4+3][lrow] = b0.w;
        Bs[lkq*4+0][lrow+64] = b1.x; Bs[lkq*4+1][lrow+64] = b1.y;
        Bs[lkq*4+2][lrow+64] = b1.z; Bs[lkq*4+3][lrow+64] = b1.w;
        __syncthreads();
#pragma unroll
        for (int kk = 0; kk < 16; kk++) {
            float4 af0 = *(const float4*)&As[kk][ty*8];
            float4 af1 = *(const float4*)&As[kk][ty*8+4];
            float4 bf0 = *(const float4*)&Bs[kk][tx*8];
            float4 bf1 = *(const float4*)&Bs[kk][tx*8+4];
            float ar[8] = {af0.x, af0.y, af0.z, af0.w, af1.x, af1.y, af1.z, af1.w};
            float br[8] = {bf0.x, bf0.y, bf0.z, bf0.w, bf1.x, bf1.y, bf1.z, bf1.w};
#pragma unroll
            for (int i = 0; i < 8; i++)
#pragma unroll
                for (int j = 0; j < 8; j++) acc[i][j] += ar[i] * br[j];
        }
    }

    float bv[8];
#pragma unroll
    for (int j = 0; j < 8; j++) bv[j] = bias[bn + tx*8 + j];

#pragma unroll
    for (int i = 0; i < 8; i++) {
        const int grow = bm + ty*8 + i;
        const size_t base = (size_t)grow * N + bn + tx*8;
        float out[8];
#pragma unroll
        for (int j = 0; j < 8; j++) out[j] = acc[i][j] + bv[j];
        if (do_relu) {
#pragma unroll
            for (int j = 0; j < 8; j++) out[j] = fmaxf(out[j], 0.f);
        }
        if (resid) {
            float4 r0 = *(const float4*)(resid + base);
            float4 r1 = *(const float4*)(resid + base + 4);
            out[0] += r0.x; out[1] += r0.y; out[2] += r0.z; out[3] += r0.w;
            out[4] += r1.x; out[5] += r1.y; out[6] += r1.z; out[7] += r1.w;
        }
        *(float4*)(C + base)     = make_float4(out[0], out[1], out[2], out[3]);
        *(float4*)(C + base + 4) = make_float4(out[4], out[5], out[6], out[7]);
    }
}

// ---------------- Flash attention (fp32), Br=Bc=64, 256 threads ----------------
// grid: (Tq/64, H, B). Layout of Q/K/V: [B*T, 1024], head h at cols h*64..h*64+63.
// smem (dynamic): Qs[64][64] | Ks[64][64] (XOR-swizzled) | Vs[64][64] | Ps[64][65] (P^T)
#define FA_SMEM_FLOATS (64*64*3 + 64*65)
#define FA_SMEM_BYTES  (FA_SMEM_FLOATS * 4)

__global__ __launch_bounds__(256) void flash_attn(
    const float* __restrict__ Q, const float* __restrict__ Kg,
    const float* __restrict__ Vg, float* __restrict__ O,
    int Tq, int Tk, int causal)
{
    extern __shared__ float sm[];
    float* Qs = sm;
    float* Ks = sm + 4096;
    float* Vs = sm + 8192;
    float* Ps = sm + 12288;

    const int tid = threadIdx.x;
    const int tx = tid & 15;
    const int ty = tid >> 4;
    const int qb = blockIdx.x * 64;
    const int h  = blockIdx.y;
    const int bb = blockIdx.z;

    const float* Qbase = Q  + (size_t)bb * Tq * D_MODEL + h * DHEAD;
    const float* Kbase = Kg + (size_t)bb * Tk * D_MODEL + h * DHEAD;
    const float* Vbase = Vg + (size_t)bb * Tk * D_MODEL + h * DHEAD;

    // Load Q tile, pre-scaled by 1/sqrt(64)
#pragma unroll
    for (int f = tid; f < 1024; f += 256) {
        int r = f >> 4, d4 = f & 15;
        float4 v = *(const float4*)(Qbase + (size_t)(qb + r) * D_MODEL + d4 * 4);
        v.x *= 0.125f; v.y *= 0.125f; v.z *= 0.125f; v.w *= 0.125f;
        *(float4*)&Qs[r*64 + d4*4] = v;
    }

    float o[4][4];
#pragma unroll
    for (int i = 0; i < 4; i++)
#pragma unroll
        for (int j = 0; j < 4; j++) o[i][j] = 0.f;
    float m[4] = {-INFINITY, -INFINITY, -INFINITY, -INFINITY};
    float l[4] = {0.f, 0.f, 0.f, 0.f};

    const int nt = causal ? (blockIdx.x + 1) : (Tk / 64);
    for (int t = 0; t < nt; t++) {
        const int kb = t * 64;
        __syncthreads();  // protect smem from previous iteration (and Q load on t=0)
#pragma unroll
        for (int f = tid; f < 1024; f += 256) {
            int r = f >> 4, d4 = f & 15;
            float4 kv = *(const float4*)(Kbase + (size_t)(kb + r) * D_MODEL + d4 * 4);
            int sd4 = (d4 ^ r) & 15;
            *(float4*)&Ks[r*64 + sd4*4] = kv;
            float4 vv = *(const float4*)(Vbase + (size_t)(kb + r) * D_MODEL + d4 * 4);
            *(float4*)&Vs[r*64 + d4*4] = vv;
        }
        __syncthreads();

        // S tile: rows r = ty + ii*16, cols c = tx + jj*16
        float s[4][4];
#pragma unroll
        for (int i = 0; i < 4; i++)
#pragma unroll
            for (int j = 0; j < 4; j++) s[i][j] = 0.f;
#pragma unroll
        for (int d4 = 0; d4 < 16; d4++) {
            float4 a[4], b[4];
#pragma unroll
            for (int ii = 0; ii < 4; ii++)
                a[ii] = *(const float4*)&Qs[(ty + ii*16)*64 + d4*4];
#pragma unroll
            for (int jj = 0; jj < 4; jj++) {
                int c = tx + jj*16;
                b[jj] = *(const float4*)&Ks[c*64 + ((d4 ^ (c & 15)) & 15)*4];
            }
#pragma unroll
            for (int ii = 0; ii < 4; ii++)
#pragma unroll
                for (int jj = 0; jj < 4; jj++)
                    s[ii][jj] += a[ii].x*b[jj].x + a[ii].y*b[jj].y
                               + a[ii].z*b[jj].z + a[ii].w*b[jj].w;
        }

        if (causal) {
#pragma unroll
            for (int ii = 0; ii < 4; ii++)
#pragma unroll
                for (int jj = 0; jj < 4; jj++)
                    if (kb + tx + jj*16 > qb + ty + ii*16) s[ii][jj] = -1e30f;
        }

        // online softmax (row r owned by the 16 lanes sharing ty within a half-warp)
#pragma unroll
        for (int ii = 0; ii < 4; ii++) {
            float mloc = fmaxf(fmaxf(s[ii][0], s[ii][1]), fmaxf(s[ii][2], s[ii][3]));
#pragma unroll
            for (int off = 8; off > 0; off >>= 1)
                mloc = fmaxf(mloc, __shfl_xor_sync(0xffffffffu, mloc, off));
            float mnew = fmaxf(m[ii], mloc);
            float alpha = __expf(m[ii] - mnew);
            float psum = 0.f;
#pragma unroll
            for (int jj = 0; jj < 4; jj++) {
                float p = __expf(s[ii][jj] - mnew);
                s[ii][jj] = p;
                psum += p;
            }
#pragma unroll
            for (int off = 8; off > 0; off >>= 1)
                psum += __shfl_xor_sync(0xffffffffu, psum, off);
            l[ii] = l[ii] * alpha + psum;
            m[ii] = mnew;
#pragma unroll
            for (int jj = 0; jj < 4; jj++) o[ii][jj] *= alpha;
        }

        // write P^T: Ps[k][r], stride 65
#pragma unroll
        for (int ii = 0; ii < 4; ii++)
#pragma unroll
            for (int jj = 0; jj < 4; jj++)
                Ps[(tx + jj*16)*65 + (ty + ii*16)] = s[ii][jj];
        __syncthreads();

        // O += P @ V ; thread owns rows ty+ii*16, cols d = tx*4..tx*4+3
#pragma unroll 8
        for (int kk = 0; kk < 64; kk++) {
            float4 bv = *(const float4*)&Vs[kk*64 + tx*4];
            float a0 = Ps[kk*65 + ty];
            float a1 = Ps[kk*65 + ty + 16];
            float a2 = Ps[kk*65 + ty + 32];
            float a3 = Ps[kk*65 + ty + 48];
            o[0][0] += a0*bv.x; o[0][1] += a0*bv.y; o[0][2] += a0*bv.z; o[0][3] += a0*bv.w;
            o[1][0] += a1*bv.x; o[1][1] += a1*bv.y; o[1][2] += a1*bv.z; o[1][3] += a1*bv.w;
            o[2][0] += a2*bv.x; o[2][1] += a2*bv.y; o[2][2] += a2*bv.z; o[2][3] += a2*bv.w;
            o[3][0] += a3*bv.x; o[3][1] += a3*bv.y; o[3][2] += a3*bv.z; o[3][3] += a3*bv.w;
        }
    }

#pragma unroll
    for (int ii = 0; ii < 4; ii++) {
        float inv = 1.f / l[ii];
        int row = qb + ty + ii*16;
        float4 out = make_float4(o[ii][0]*inv, o[ii][1]*inv, o[ii][2]*inv, o[ii][3]*inv);
        *(float4*)(O + ((size_t)bb * Tq + row) * D_MODEL + h * DHEAD + tx*4) = out;
    }
}

// ---------------- Residual already fused in GEMM; LN over rows of 1024 ----------------
__global__ __launch_bounds__(256) void ln_kernel(
    const float* __restrict__ in, const float* __restrict__ g,
    const float* __restrict__ b, float* __restrict__ out)
{
    const int row = blockIdx.x;
    const int tid = threadIdx.x;
    float4 v = ((const float4*)(in + (size_t)row * D_MODEL))[tid];
    float s  = v.x + v.y + v.z + v.w;
    float ss = v.x*v.x + v.y*v.y + v.z*v.z + v.w*v.w;
#pragma unroll
    for (int off = 16; off > 0; off >>= 1) {
        s  += __shfl_xor_sync(0xffffffffu, s,  off);
        ss += __shfl_xor_sync(0xffffffffu, ss, off);
    }
    __shared__ float ws[8], wss[8];
    __shared__ float s_mu, s_inv;
    const int warp = tid >> 5, lane = tid & 31;
    if (lane == 0) { ws[warp] = s; wss[warp] = ss; }
    __syncthreads();
    if (tid == 0) {
        float ts = 0.f, tss = 0.f;
#pragma unroll
        for (int w = 0; w < 8; w++) { ts += ws[w]; tss += wss[w]; }
        float mu = ts * (1.f / D_MODEL);
        float var = tss * (1.f / D_MODEL) - mu * mu;
        s_mu = mu;
        s_inv = rsqrtf(var + 1e-5f);
    }
    __syncthreads();
    float mu = s_mu, inv = s_inv;
    float4 gg = ((const float4*)g)[tid];
    float4 bb = ((const float4*)b)[tid];
    float4 r;
    r.x = (v.x - mu) * inv * gg.x + bb.x;
    r.y = (v.y - mu) * inv * gg.y + bb.y;
    r.z = (v.z - mu) * inv * gg.z + bb.z;
    r.w = (v.w - mu) * inv * gg.w + bb.w;
    ((float4*)(out + (size_t)row * D_MODEL))[tid] = r;
}

// ---------------- orchestration ----------------
extern "C" void kernel_launch(void* const* d_in, const int* in_sizes, int n_in,
                              void* d_out, int out_size)
{
    const float* x     = (const float*)d_in[0];
    const float* enc   = (const float*)d_in[1];
    // d_in[2] = src_mask (all ones), d_in[3] = tgt_mask (causal tril) — handled analytically
    const float* sa_Wq = (const float*)d_in[4];
    const float* sa_bq = (const float*)d_in[5];
    const float* sa_Wk = (const float*)d_in[6];
    const float* sa_bk = (const float*)d_in[7];
    const float* sa_Wv = (const float*)d_in[8];
    const float* sa_bv = (const float*)d_in[9];
    const float* sa_Wo = (const float*)d_in[10];
    const float* sa_bo = (const float*)d_in[11];
    const float* ca_Wq = (const float*)d_in[12];
    const float* ca_bq = (const float*)d_in[13];
    const float* ca_Wk = (const float*)d_in[14];
    const float* ca_bk = (const float*)d_in[15];
    const float* ca_Wv = (const float*)d_in[16];
    const float* ca_bv = (const float*)d_in[17];
    const float* ca_Wo = (const float*)d_in[18];
    const float* ca_bo = (const float*)d_in[19];
    const float* ff_W1 = (const float*)d_in[20];
    const float* ff_b1 = (const float*)d_in[21];
    const float* ff_W2 = (const float*)d_in[22];
    const float* ff_b2 = (const float*)d_in[23];
    const float* ln1_g = (const float*)d_in[24];
    const float* ln1_b = (const float*)d_in[25];
    const float* ln2_g = (const float*)d_in[26];
    const float* ln2_b = (const float*)d_in[27];
    const float* ln3_g = (const float*)d_in[28];
    const float* ln3_b = (const float*)d_in[29];

    float *q, *k, *v, *ctx, *tmp, *x1, *x2, *ffh;
    cudaGetSymbolAddress((void**)&q,   g_q);
    cudaGetSymbolAddress((void**)&k,   g_k);
    cudaGetSymbolAddress((void**)&v,   g_v);
    cudaGetSymbolAddress((void**)&ctx, g_ctx);
    cudaGetSymbolAddress((void**)&tmp, g_tmp);
    cudaGetSymbolAddress((void**)&x1,  g_x1);
    cudaGetSymbolAddress((void**)&x2,  g_x2);
    cudaGetSymbolAddress((void**)&ffh, g_ffh);

    cudaFuncSetAttribute(flash_attn, cudaFuncAttributeMaxDynamicSharedMemorySize, FA_SMEM_BYTES);

    dim3 gp(D_MODEL/128, MROWS/128);        // (8, 32) projection GEMMs
    dim3 gf1(DFF_/128,  MROWS/128);         // (32, 32) FFN up
    dim3 gfa(TT/64, NHEAD, BB);             // flash attention

    // --- self attention ---
    sgemm_nt<<<gp, 256>>>(x, sa_Wq, sa_bq, nullptr, q, MROWS, D_MODEL, D_MODEL, 0);
    sgemm_nt<<<gp, 256>>>(x, sa_Wk, sa_bk, nullptr, k, MROWS, D_MODEL, D_MODEL, 0);
    sgemm_nt<<<gp, 256>>>(x, sa_Wv, sa_bv, nullptr, v, MROWS, D_MODEL, D_MODEL, 0);
    flash_attn<<<gfa, 256, FA_SMEM_BYTES>>>(q, k, v, ctx, TT, TT, 1);
    sgemm_nt<<<gp, 256>>>(ctx, sa_Wo, sa_bo, x, tmp, MROWS, D_MODEL, D_MODEL, 0);
    ln_kernel<<<MROWS, 256>>>(tmp, ln1_g, ln1_b, x1);

    // --- cross attention ---
    sgemm_nt<<<gp, 256>>>(x1,  ca_Wq, ca_bq, nullptr, q, MROWS, D_MODEL, D_MODEL, 0);
    sgemm_nt<<<gp, 256>>>(enc, ca_Wk, ca_bk, nullptr, k, MROWS, D_MODEL, D_MODEL, 0);
    sgemm_nt<<<gp, 256>>>(enc, ca_Wv, ca_bv, nullptr, v, MROWS, D_MODEL, D_MODEL, 0);
    flash_attn<<<gfa, 256, FA_SMEM_BYTES>>>(q, k, v, ctx, TT, SSEQ, 0);
    sgemm_nt<<<gp, 256>>>(ctx, ca_Wo, ca_bo, x1, tmp, MROWS, D_MODEL, D_MODEL, 0);
    ln_kernel<<<MROWS, 256>>>(tmp, ln2_g, ln2_b, x2);

    // --- FFN ---
    sgemm_nt<<<gf1, 256>>>(x2,  ff_W1, ff_b1, nullptr, ffh, MROWS, DFF_,    D_MODEL, 1);
    sgemm_nt<<<gp, 256>>>(ffh, ff_W2, ff_b2, x2,      tmp, MROWS, D_MODEL, DFF_,    0);
    ln_kernel<<<MROWS, 256>>>(tmp, ln3_g, ln3_b, (float*)d_out);
}

// round 3
// speedup vs baseline: 1.9596x; 1.9596x over previous
#include <cuda_runtime.h>
#include <math.h>
#include <stdint.h>

#define D_MODEL 1024
#define NHEAD   16
#define DHEAD   64
#define BB      2
#define TT      2048
#define SSEQ    2048
#define MROWS   (BB*TT)      // 4096
#define DFF_    4096

// ---------------- scratch (device globals; no runtime allocation) ----------------
__device__ float g_q  [MROWS * D_MODEL];
__device__ float g_k  [MROWS * D_MODEL];
__device__ float g_v  [MROWS * D_MODEL];
__device__ float g_ctx[MROWS * D_MODEL];
__device__ float g_tmp[MROWS * D_MODEL];
__device__ float g_x1 [MROWS * D_MODEL];
__device__ float g_x2 [MROWS * D_MODEL];
__device__ float g_ffh[(size_t)MROWS * DFF_];

// ================= TF32 tensor-core GEMM: C = A(MxK) @ B(NxK)^T + bias [+resid][relu]
// 128x128 tile, BK=16, 256 threads (8 warps), warp tile 64x32 via m16n8k8 mma.
#define AST 20   // smem row stride (floats): conflict-free for mma fragment loads

__device__ __forceinline__ uint32_t f2tf32(float f) {
    uint32_t u;
    asm("cvt.rna.tf32.f32 %0, %1;" : "=r"(u) : "f"(f));
    return u;
}

__global__ __launch_bounds__(256) void gemm_tf32(
    const float* __restrict__ A, const float* __restrict__ B,
    const float* __restrict__ bias, const float* __restrict__ resid,
    float* __restrict__ C, int M, int N, int K, int do_relu)
{
    __shared__ uint32_t As[128 * AST];
    __shared__ uint32_t Bs[128 * AST];

    const int tid  = threadIdx.x;
    const int warp = tid >> 5;
    const int lane = tid & 31;
    const int g    = lane >> 2;   // group 0..7
    const int tg   = lane & 3;    // 0..3
    const int warp_m = (warp & 1) * 64;
    const int warp_n = (warp >> 1) * 32;
    const int bm = blockIdx.y * 128;
    const int bn = blockIdx.x * 128;

    float acc[4][4][4];
#pragma unroll
    for (int i = 0; i < 4; i++)
#pragma unroll
        for (int j = 0; j < 4; j++)
#pragma unroll
            for (int c = 0; c < 4; c++) acc[i][j][c] = 0.f;

    // gmem load mapping: 512 float4 per tile; thread covers f=tid (rows 0..63)
    // and f=tid+256 (rows 64..127). row = f>>2, c4 = f&3.
    const int r0 = tid >> 2;
    const int c4 = tid & 3;

    uint4 pa0, pa1, pb0, pb1;
    {
        const float4 a0 = *(const float4*)(A + (size_t)(bm + r0)      * K + c4 * 4);
        const float4 a1 = *(const float4*)(A + (size_t)(bm + r0 + 64) * K + c4 * 4);
        const float4 b0 = *(const float4*)(B + (size_t)(bn + r0)      * K + c4 * 4);
        const float4 b1 = *(const float4*)(B + (size_t)(bn + r0 + 64) * K + c4 * 4);
        pa0 = make_uint4(f2tf32(a0.x), f2tf32(a0.y), f2tf32(a0.z), f2tf32(a0.w));
        pa1 = make_uint4(f2tf32(a1.x), f2tf32(a1.y), f2tf32(a1.z), f2tf32(a1.w));
        pb0 = make_uint4(f2tf32(b0.x), f2tf32(b0.y), f2tf32(b0.z), f2tf32(b0.w));
        pb1 = make_uint4(f2tf32(b1.x), f2tf32(b1.y), f2tf32(b1.z), f2tf32(b1.w));
    }

    const int nk = K >> 4;
    for (int kt = 0; kt < nk; kt++) {
        __syncthreads();
        *(uint4*)&As[r0 * AST + c4 * 4]        = pa0;
        *(uint4*)&As[(r0 + 64) * AST + c4 * 4] = pa1;
        *(uint4*)&Bs[r0 * AST + c4 * 4]        = pb0;
        *(uint4*)&Bs[(r0 + 64) * AST + c4 * 4] = pb1;
        __syncthreads();

        if (kt + 1 < nk) {
            const int k0 = (kt + 1) << 4;
            const float4 a0 = *(const float4*)(A + (size_t)(bm + r0)      * K + k0 + c4 * 4);
            const float4 a1 = *(const float4*)(A + (size_t)(bm + r0 + 64) * K + k0 + c4 * 4);
            const float4 b0 = *(const float4*)(B + (size_t)(bn + r0)      * K + k0 + c4 * 4);
            const float4 b1 = *(const float4*)(B + (size_t)(bn + r0 + 64) * K + k0 + c4 * 4);
            pa0 = make_uint4(f2tf32(a0.x), f2tf32(a0.y), f2tf32(a0.z), f2tf32(a0.w));
            pa1 = make_uint4(f2tf32(a1.x), f2tf32(a1.y), f2tf32(a1.z), f2tf32(a1.w));
            pb0 = make_uint4(f2tf32(b0.x), f2tf32(b0.y), f2tf32(b0.z), f2tf32(b0.w));
            pb1 = make_uint4(f2tf32(b1.x), f2tf32(b1.y), f2tf32(b1.z), f2tf32(b1.w));
        }

#pragma unroll
        for (int ks = 0; ks < 2; ks++) {
            const int k0 = ks * 8;
            uint32_t af[4][4], bf[4][2];
#pragma unroll
            for (int i = 0; i < 4; i++) {
                const int row = warp_m + i * 16 + g;
                af[i][0] = As[row * AST + k0 + tg];
                af[i][1] = As[(row + 8) * AST + k0 + tg];
                af[i][2] = As[row * AST + k0 + tg + 4];
                af[i][3] = As[(row + 8) * AST + k0 + tg + 4];
            }
#pragma unroll
            for (int j = 0; j < 4; j++) {
                const int col = warp_n + j * 8 + g;
                bf[j][0] = Bs[col * AST + k0 + tg];
                bf[j][1] = Bs[col * AST + k0 + tg + 4];
            }
#pragma unroll
            for (int i = 0; i < 4; i++)
#pragma unroll
                for (int j = 0; j < 4; j++) {
                    asm volatile(
                        "mma.sync.aligned.m16n8k8.row.col.f32.tf32.tf32.f32 "
                        "{%0,%1,%2,%3}, {%4,%5,%6,%7}, {%8,%9}, {%0,%1,%2,%3};"
                        : "+f"(acc[i][j][0]), "+f"(acc[i][j][1]),
                          "+f"(acc[i][j][2]), "+f"(acc[i][j][3])
                        : "r"(af[i][0]), "r"(af[i][1]), "r"(af[i][2]), "r"(af[i][3]),
                          "r"(bf[j][0]), "r"(bf[j][1]));
                }
        }
    }

    // epilogue: c0 -> (row g,   col tg*2), c1 -> col+1, c2 -> (row g+8), c3 -> col+1
#pragma unroll
    for (int j = 0; j < 4; j++) {
        const int col = bn + warp_n + j * 8 + tg * 2;
        const float bx = bias[col], by = bias[col + 1];
#pragma unroll
        for (int i = 0; i < 4; i++) {
            const int row0 = bm + warp_m + i * 16 + g;
            const int row1 = row0 + 8;
            float o00 = acc[i][j][0] + bx, o01 = acc[i][j][1] + by;
            float o10 = acc[i][j][2] + bx, o11 = acc[i][j][3] + by;
            if (do_relu) {
                o00 = fmaxf(o00, 0.f); o01 = fmaxf(o01, 0.f);
                o10 = fmaxf(o10, 0.f); o11 = fmaxf(o11, 0.f);
            }
            if (resid) {
                const float2 r0v = *(const float2*)(resid + (size_t)row0 * N + col);
                const float2 r1v = *(const float2*)(resid + (size_t)row1 * N + col);
                o00 += r0v.x; o01 += r0v.y; o10 += r1v.x; o11 += r1v.y;
            }
            *(float2*)(C + (size_t)row0 * N + col) = make_float2(o00, o01);
            *(float2*)(C + (size_t)row1 * N + col) = make_float2(o10, o11);
        }
    }
}

// ---------------- Flash attention (fp32), Br=Bc=64, 256 threads ----------------
#define FA_SMEM_FLOATS (64*64*3 + 64*65)
#define FA_SMEM_BYTES  (FA_SMEM_FLOATS * 4)

__global__ __launch_bounds__(256) void flash_attn(
    const float* __restrict__ Q, const float* __restrict__ Kg,
    const float* __restrict__ Vg, float* __restrict__ O,
    int Tq, int Tk, int causal)
{
    extern __shared__ float sm[];
    float* Qs = sm;
    float* Ks = sm + 4096;
    float* Vs = sm + 8192;
    float* Ps = sm + 12288;

    const int tid = threadIdx.x;
    const int tx = tid & 15;
    const int ty = tid >> 4;
    const int qb = blockIdx.x * 64;
    const int h  = blockIdx.y;
    const int bb = blockIdx.z;

    const float* Qbase = Q  + (size_t)bb * Tq * D_MODEL + h * DHEAD;
    const float* Kbase = Kg + (size_t)bb * Tk * D_MODEL + h * DHEAD;
    const float* Vbase = Vg + (size_t)bb * Tk * D_MODEL + h * DHEAD;

#pragma unroll
    for (int f = tid; f < 1024; f += 256) {
        int r = f >> 4, d4 = f & 15;
        float4 v = *(const float4*)(Qbase + (size_t)(qb + r) * D_MODEL + d4 * 4);
        v.x *= 0.125f; v.y *= 0.125f; v.z *= 0.125f; v.w *= 0.125f;
        *(float4*)&Qs[r*64 + d4*4] = v;
    }

    float o[4][4];
#pragma unroll
    for (int i = 0; i < 4; i++)
#pragma unroll
        for (int j = 0; j < 4; j++) o[i][j] = 0.f;
    float m[4] = {-INFINITY, -INFINITY, -INFINITY, -INFINITY};
    float l[4] = {0.f, 0.f, 0.f, 0.f};

    const int nt = causal ? (blockIdx.x + 1) : (Tk / 64);
    for (int t = 0; t < nt; t++) {
        const int kb = t * 64;
        __syncthreads();
#pragma unroll
        for (int f = tid; f < 1024; f += 256) {
            int r = f >> 4, d4 = f & 15;
            float4 kv = *(const float4*)(Kbase + (size_t)(kb + r) * D_MODEL + d4 * 4);
            int sd4 = (d4 ^ r) & 15;
            *(float4*)&Ks[r*64 + sd4*4] = kv;
            float4 vv = *(const float4*)(Vbase + (size_t)(kb + r) * D_MODEL + d4 * 4);
            *(float4*)&Vs[r*64 + d4*4] = vv;
        }
        __syncthreads();

        float s[4][4];
#pragma unroll
        for (int i = 0; i < 4; i++)
#pragma unroll
            for (int j = 0; j < 4; j++) s[i][j] = 0.f;
#pragma unroll
        for (int d4 = 0; d4 < 16; d4++) {
            float4 a[4], b[4];
#pragma unroll
            for (int ii = 0; ii < 4; ii++)
                a[ii] = *(const float4*)&Qs[(ty + ii*16)*64 + d4*4];
#pragma unroll
            for (int jj = 0; jj < 4; jj++) {
                int c = tx + jj*16;
                b[jj] = *(const float4*)&Ks[c*64 + ((d4 ^ (c & 15)) & 15)*4];
            }
#pragma unroll
            for (int ii = 0; ii < 4; ii++)
#pragma unroll
                for (int jj = 0; jj < 4; jj++)
                    s[ii][jj] += a[ii].x*b[jj].x + a[ii].y*b[jj].y
                               + a[ii].z*b[jj].z + a[ii].w*b[jj].w;
        }

        if (causal) {
#pragma unroll
            for (int ii = 0; ii < 4; ii++)
#pragma unroll
                for (int jj = 0; jj < 4; jj++)
                    if (kb + tx + jj*16 > qb + ty + ii*16) s[ii][jj] = -1e30f;
        }

#pragma unroll
        for (int ii = 0; ii < 4; ii++) {
            float mloc = fmaxf(fmaxf(s[ii][0], s[ii][1]), fmaxf(s[ii][2], s[ii][3]));
#pragma unroll
            for (int off = 8; off > 0; off >>= 1)
                mloc = fmaxf(mloc, __shfl_xor_sync(0xffffffffu, mloc, off));
            float mnew = fmaxf(m[ii], mloc);
            float alpha = __expf(m[ii] - mnew);
            float psum = 0.f;
#pragma unroll
            for (int jj = 0; jj < 4; jj++) {
                float p = __expf(s[ii][jj] - mnew);
                s[ii][jj] = p;
                psum += p;
            }
#pragma unroll
            for (int off = 8; off > 0; off >>= 1)
                psum += __shfl_xor_sync(0xffffffffu, psum, off);
            l[ii] = l[ii] * alpha + psum;
            m[ii] = mnew;
#pragma unroll
            for (int jj = 0; jj < 4; jj++) o[ii][jj] *= alpha;
        }

#pragma unroll
        for (int ii = 0; ii < 4; ii++)
#pragma unroll
            for (int jj = 0; jj < 4; jj++)
                Ps[(tx + jj*16)*65 + (ty + ii*16)] = s[ii][jj];
        __syncthreads();

#pragma unroll 8
        for (int kk = 0; kk < 64; kk++) {
            float4 bv = *(const float4*)&Vs[kk*64 + tx*4];
            float a0 = Ps[kk*65 + ty];
            float a1 = Ps[kk*65 + ty + 16];
            float a2 = Ps[kk*65 + ty + 32];
            float a3 = Ps[kk*65 + ty + 48];
            o[0][0] += a0*bv.x; o[0][1] += a0*bv.y; o[0][2] += a0*bv.z; o[0][3] += a0*bv.w;
            o[1][0] += a1*bv.x; o[1][1] += a1*bv.y; o[1][2] += a1*bv.z; o[1][3] += a1*bv.w;
            o[2][0] += a2*bv.x; o[2][1] += a2*bv.y; o[2][2] += a2*bv.z; o[2][3] += a2*bv.w;
            o[3][0] += a3*bv.x; o[3][1] += a3*bv.y; o[3][2] += a3*bv.z; o[3][3] += a3*bv.w;
        }
    }

#pragma unroll
    for (int ii = 0; ii < 4; ii++) {
        float inv = 1.f / l[ii];
        int row = qb + ty + ii*16;
        float4 out = make_float4(o[ii][0]*inv, o[ii][1]*inv, o[ii][2]*inv, o[ii][3]*inv);
        *(float4*)(O + ((size_t)bb * Tq + row) * D_MODEL + h * DHEAD + tx*4) = out;
    }
}

// ---------------- LN over rows of 1024 ----------------
__global__ __launch_bounds__(256) void ln_kernel(
    const float* __restrict__ in, const float* __restrict__ g,
    const float* __restrict__ b, float* __restrict__ out)
{
    const int row = blockIdx.x;
    const int tid = threadIdx.x;
    float4 v = ((const float4*)(in + (size_t)row * D_MODEL))[tid];
    float s  = v.x + v.y + v.z + v.w;
    float ss = v.x*v.x + v.y*v.y + v.z*v.z + v.w*v.w;
#pragma unroll
    for (int off = 16; off > 0; off >>= 1) {
        s  += __shfl_xor_sync(0xffffffffu, s,  off);
        ss += __shfl_xor_sync(0xffffffffu, ss, off);
    }
    __shared__ float ws[8], wss[8];
    __shared__ float s_mu, s_inv;
    const int warp = tid >> 5, lane = tid & 31;
    if (lane == 0) { ws[warp] = s; wss[warp] = ss; }
    __syncthreads();
    if (tid == 0) {
        float ts = 0.f, tss = 0.f;
#pragma unroll
        for (int w = 0; w < 8; w++) { ts += ws[w]; tss += wss[w]; }
        float mu = ts * (1.f / D_MODEL);
        float var = tss * (1.f / D_MODEL) - mu * mu;
        s_mu = mu;
        s_inv = rsqrtf(var + 1e-5f);
    }
    __syncthreads();
    float mu = s_mu, inv = s_inv;
    float4 gg = ((const float4*)g)[tid];
    float4 bb = ((const float4*)b)[tid];
    float4 r;
    r.x = (v.x - mu) * inv * gg.x + bb.x;
    r.y = (v.y - mu) * inv * gg.y + bb.y;
    r.z = (v.z - mu) * inv * gg.z + bb.z;
    r.w = (v.w - mu) * inv * gg.w + bb.w;
    ((float4*)(out + (size_t)row * D_MODEL))[tid] = r;
}

// ---------------- orchestration ----------------
extern "C" void kernel_launch(void* const* d_in, const int* in_sizes, int n_in,
                              void* d_out, int out_size)
{
    const float* x     = (const float*)d_in[0];
    const float* enc   = (const float*)d_in[1];
    const float* sa_Wq = (const float*)d_in[4];
    const float* sa_bq = (const float*)d_in[5];
    const float* sa_Wk = (const float*)d_in[6];
    const float* sa_bk = (const float*)d_in[7];
    const float* sa_Wv = (const float*)d_in[8];
    const float* sa_bv = (const float*)d_in[9];
    const float* sa_Wo = (const float*)d_in[10];
    const float* sa_bo = (const float*)d_in[11];
    const float* ca_Wq = (const float*)d_in[12];
    const float* ca_bq = (const float*)d_in[13];
    const float* ca_Wk = (const float*)d_in[14];
    const float* ca_bk = (const float*)d_in[15];
    const float* ca_Wv = (const float*)d_in[16];
    const float* ca_bv = (const float*)d_in[17];
    const float* ca_Wo = (const float*)d_in[18];
    const float* ca_bo = (const float*)d_in[19];
    const float* ff_W1 = (const float*)d_in[20];
    const float* ff_b1 = (const float*)d_in[21];
    const float* ff_W2 = (const float*)d_in[22];
    const float* ff_b2 = (const float*)d_in[23];
    const float* ln1_g = (const float*)d_in[24];
    const float* ln1_b = (const float*)d_in[25];
    const float* ln2_g = (const float*)d_in[26];
    const float* ln2_b = (const float*)d_in[27];
    const float* ln3_g = (const float*)d_in[28];
    const float* ln3_b = (const float*)d_in[29];

    float *q, *k, *v, *ctx, *tmp, *x1, *x2, *ffh;
    cudaGetSymbolAddress((void**)&q,   g_q);
    cudaGetSymbolAddress((void**)&k,   g_k);
    cudaGetSymbolAddress((void**)&v,   g_v);
    cudaGetSymbolAddress((void**)&ctx, g_ctx);
    cudaGetSymbolAddress((void**)&tmp, g_tmp);
    cudaGetSymbolAddress((void**)&x1,  g_x1);
    cudaGetSymbolAddress((void**)&x2,  g_x2);
    cudaGetSymbolAddress((void**)&ffh, g_ffh);

    cudaFuncSetAttribute(flash_attn, cudaFuncAttributeMaxDynamicSharedMemorySize, FA_SMEM_BYTES);

    dim3 gp(D_MODEL/128, MROWS/128);        // (8, 32) projection GEMMs
    dim3 gf1(DFF_/128,  MROWS/128);         // (32, 32) FFN up
    dim3 gfa(TT/64, NHEAD, BB);             // flash attention

    // --- self attention ---
    gemm_tf32<<<gp, 256>>>(x, sa_Wq, sa_bq, nullptr, q, MROWS, D_MODEL, D_MODEL, 0);
    gemm_tf32<<<gp, 256>>>(x, sa_Wk, sa_bk, nullptr, k, MROWS, D_MODEL, D_MODEL, 0);
    gemm_tf32<<<gp, 256>>>(x, sa_Wv, sa_bv, nullptr, v, MROWS, D_MODEL, D_MODEL, 0);
    flash_attn<<<gfa, 256, FA_SMEM_BYTES>>>(q, k, v, ctx, TT, TT, 1);
    gemm_tf32<<<gp, 256>>>(ctx, sa_Wo, sa_bo, x, tmp, MROWS, D_MODEL, D_MODEL, 0);
    ln_kernel<<<MROWS, 256>>>(tmp, ln1_g, ln1_b, x1);

    // --- cross attention ---
    gemm_tf32<<<gp, 256>>>(x1,  ca_Wq, ca_bq, nullptr, q, MROWS, D_MODEL, D_MODEL, 0);
    gemm_tf32<<<gp, 256>>>(enc, ca_Wk, ca_bk, nullptr, k, MROWS, D_MODEL, D_MODEL, 0);
    gemm_tf32<<<gp, 256>>>(enc, ca_Wv, ca_bv, nullptr, v, MROWS, D_MODEL, D_MODEL, 0);
    flash_attn<<<gfa, 256, FA_SMEM_BYTES>>>(q, k, v, ctx, TT, SSEQ, 0);
    gemm_tf32<<<gp, 256>>>(ctx, ca_Wo, ca_bo, x1, tmp, MROWS, D_MODEL, D_MODEL, 0);
    ln_kernel<<<MROWS, 256>>>(tmp, ln2_g, ln2_b, x2);

    // --- FFN ---
    gemm_tf32<<<gf1, 256>>>(x2,  ff_W1, ff_b1, nullptr, ffh, MROWS, DFF_,    D_MODEL, 1);
    gemm_tf32<<<gp, 256>>>(ffh, ff_W2, ff_b2, x2,      tmp, MROWS, D_MODEL, DFF_,    0);
    ln_kernel<<<MROWS, 256>>>(tmp, ln3_g, ln3_b, (float*)d_out);
}

// round 4
// speedup vs baseline: 2.2241x; 1.1350x over previous
#include <cuda_runtime.h>
#include <math.h>
#include <stdint.h>

#define D_MODEL 1024
#define NHEAD   16
#define DHEAD   64
#define BB      2
#define TT      2048
#define SSEQ    2048
#define MROWS   (BB*TT)      // 4096
#define DFF_    4096

// ---------------- scratch (device globals; no runtime allocation) ----------------
__device__ float g_q  [MROWS * D_MODEL];
__device__ float g_k  [MROWS * D_MODEL];
__device__ float g_v  [MROWS * D_MODEL];
__device__ float g_ctx[MROWS * D_MODEL];
__device__ float g_tmp[MROWS * D_MODEL];
__device__ float g_x1 [MROWS * D_MODEL];
__device__ float g_x2 [MROWS * D_MODEL];
__device__ float g_ffh[(size_t)MROWS * DFF_];

__device__ __forceinline__ uint32_t f2tf32(float f) {
    uint32_t u;
    asm("cvt.rna.tf32.f32 %0, %1;" : "=r"(u) : "f"(f));
    return u;
}

__device__ __forceinline__ void mma_tf32(
    float* c, uint32_t a0, uint32_t a1, uint32_t a2, uint32_t a3,
    uint32_t b0, uint32_t b1)
{
    asm volatile(
        "mma.sync.aligned.m16n8k8.row.col.f32.tf32.tf32.f32 "
        "{%0,%1,%2,%3}, {%4,%5,%6,%7}, {%8,%9}, {%0,%1,%2,%3};"
        : "+f"(c[0]), "+f"(c[1]), "+f"(c[2]), "+f"(c[3])
        : "r"(a0), "r"(a1), "r"(a2), "r"(a3), "r"(b0), "r"(b1));
}

// ================= TF32 tensor-core GEMM: C = A(MxK) @ B(NxK)^T + bias [+resid][relu]
// 128x128 tile, BK=16, 256 threads (8 warps), warp tile 64x32, double-buffered smem.
#define AST 20   // smem row stride (floats): conflict-free for mma fragment loads

__global__ __launch_bounds__(256) void gemm_tf32(
    const float* __restrict__ A, const float* __restrict__ B,
    const float* __restrict__ bias, const float* __restrict__ resid,
    float* __restrict__ C, int M, int N, int K, int do_relu)
{
    __shared__ uint32_t As[2][128 * AST];
    __shared__ uint32_t Bs[2][128 * AST];

    const int tid  = threadIdx.x;
    const int warp = tid >> 5;
    const int lane = tid & 31;
    const int g    = lane >> 2;
    const int tg   = lane & 3;
    const int warp_m = (warp & 1) * 64;
    const int warp_n = (warp >> 1) * 32;
    const int bm = blockIdx.y * 128;
    const int bn = blockIdx.x * 128;

    float acc[4][4][4];
#pragma unroll
    for (int i = 0; i < 4; i++)
#pragma unroll
        for (int j = 0; j < 4; j++)
#pragma unroll
            for (int c = 0; c < 4; c++) acc[i][j][c] = 0.f;

    const int r0 = tid >> 2;
    const int c4 = tid & 3;

    uint4 pa0, pa1, pb0, pb1;
    {
        const float4 a0 = *(const float4*)(A + (size_t)(bm + r0)      * K + c4 * 4);
        const float4 a1 = *(const float4*)(A + (size_t)(bm + r0 + 64) * K + c4 * 4);
        const float4 b0 = *(const float4*)(B + (size_t)(bn + r0)      * K + c4 * 4);
        const float4 b1 = *(const float4*)(B + (size_t)(bn + r0 + 64) * K + c4 * 4);
        pa0 = make_uint4(f2tf32(a0.x), f2tf32(a0.y), f2tf32(a0.z), f2tf32(a0.w));
        pa1 = make_uint4(f2tf32(a1.x), f2tf32(a1.y), f2tf32(a1.z), f2tf32(a1.w));
        pb0 = make_uint4(f2tf32(b0.x), f2tf32(b0.y), f2tf32(b0.z), f2tf32(b0.w));
        pb1 = make_uint4(f2tf32(b1.x), f2tf32(b1.y), f2tf32(b1.z), f2tf32(b1.w));
    }
    *(uint4*)&As[0][r0 * AST + c4 * 4]        = pa0;
    *(uint4*)&As[0][(r0 + 64) * AST + c4 * 4] = pa1;
    *(uint4*)&Bs[0][r0 * AST + c4 * 4]        = pb0;
    *(uint4*)&Bs[0][(r0 + 64) * AST + c4 * 4] = pb1;
    __syncthreads();

    const int nk = K >> 4;
    for (int kt = 0; kt < nk; kt++) {
        if (kt + 1 < nk) {
            const int k0 = (kt + 1) << 4;
            const float4 a0 = *(const float4*)(A + (size_t)(bm + r0)      * K + k0 + c4 * 4);
            const float4 a1 = *(const float4*)(A + (size_t)(bm + r0 + 64) * K + k0 + c4 * 4);
            const float4 b0 = *(const float4*)(B + (size_t)(bn + r0)      * K + k0 + c4 * 4);
            const float4 b1 = *(const float4*)(B + (size_t)(bn + r0 + 64) * K + k0 + c4 * 4);
            pa0 = make_uint4(f2tf32(a0.x), f2tf32(a0.y), f2tf32(a0.z), f2tf32(a0.w));
            pa1 = make_uint4(f2tf32(a1.x), f2tf32(a1.y), f2tf32(a1.z), f2tf32(a1.w));
            pb0 = make_uint4(f2tf32(b0.x), f2tf32(b0.y), f2tf32(b0.z), f2tf32(b0.w));
            pb1 = make_uint4(f2tf32(b1.x), f2tf32(b1.y), f2tf32(b1.z), f2tf32(b1.w));
        }

        const uint32_t* Ab = As[kt & 1];
        const uint32_t* Bb = Bs[kt & 1];
#pragma unroll
        for (int ks = 0; ks < 2; ks++) {
            const int k0 = ks * 8;
            uint32_t af[4][4], bf[4][2];
#pragma unroll
            for (int i = 0; i < 4; i++) {
                const int row = warp_m + i * 16 + g;
                af[i][0] = Ab[row * AST + k0 + tg];
                af[i][1] = Ab[(row + 8) * AST + k0 + tg];
                af[i][2] = Ab[row * AST + k0 + tg + 4];
                af[i][3] = Ab[(row + 8) * AST + k0 + tg + 4];
            }
#pragma unroll
            for (int j = 0; j < 4; j++) {
                const int col = warp_n + j * 8 + g;
                bf[j][0] = Bb[col * AST + k0 + tg];
                bf[j][1] = Bb[col * AST + k0 + tg + 4];
            }
#pragma unroll
            for (int i = 0; i < 4; i++)
#pragma unroll
                for (int j = 0; j < 4; j++)
                    mma_tf32(acc[i][j], af[i][0], af[i][1], af[i][2], af[i][3],
                             bf[j][0], bf[j][1]);
        }

        if (kt + 1 < nk) {
            uint32_t* An = As[(kt + 1) & 1];
            uint32_t* Bn = Bs[(kt + 1) & 1];
            *(uint4*)&An[r0 * AST + c4 * 4]        = pa0;
            *(uint4*)&An[(r0 + 64) * AST + c4 * 4] = pa1;
            *(uint4*)&Bn[r0 * AST + c4 * 4]        = pb0;
            *(uint4*)&Bn[(r0 + 64) * AST + c4 * 4] = pb1;
            __syncthreads();
        }
    }

#pragma unroll
    for (int j = 0; j < 4; j++) {
        const int col = bn + warp_n + j * 8 + tg * 2;
        const float bx = bias[col], by = bias[col + 1];
#pragma unroll
        for (int i = 0; i < 4; i++) {
            const int row0 = bm + warp_m + i * 16 + g;
            const int row1 = row0 + 8;
            float o00 = acc[i][j][0] + bx, o01 = acc[i][j][1] + by;
            float o10 = acc[i][j][2] + bx, o11 = acc[i][j][3] + by;
            if (do_relu) {
                o00 = fmaxf(o00, 0.f); o01 = fmaxf(o01, 0.f);
                o10 = fmaxf(o10, 0.f); o11 = fmaxf(o11, 0.f);
            }
            if (resid) {
                const float2 r0v = *(const float2*)(resid + (size_t)row0 * N + col);
                const float2 r1v = *(const float2*)(resid + (size_t)row1 * N + col);
                o00 += r0v.x; o01 += r0v.y; o10 += r1v.x; o11 += r1v.y;
            }
            *(float2*)(C + (size_t)row0 * N + col) = make_float2(o00, o01);
            *(float2*)(C + (size_t)row1 * N + col) = make_float2(o10, o11);
        }
    }
}

// ================= Flash attention with TF32 mma. Br=Bc=64, 128 threads (4 warps).
// Warp w owns Q rows w*16..w*16+15. S=Q@K^T and O+=P@V both via m16n8k8.
#define QST 68   // stride for Qs/Ks/Ps: 68 % 32 == 4 -> 4g+tg conflict-free
#define VST 72   // stride for Vs:       72 % 32 == 8 -> 8tg+g conflict-free
#define FA2_SMEM_U32 (64*QST*3 + 64*VST)
#define FA2_SMEM_BYTES (FA2_SMEM_U32 * 4)

__global__ __launch_bounds__(128) void flash_attn_mma(
    const float* __restrict__ Q, const float* __restrict__ Kg,
    const float* __restrict__ Vg, float* __restrict__ O,
    int Tq, int Tk, int causal)
{
    extern __shared__ uint32_t smu[];
    uint32_t* Qs = smu;
    uint32_t* Ks = smu + 64 * QST;
    uint32_t* Ps = smu + 2 * 64 * QST;
    uint32_t* Vs = smu + 3 * 64 * QST;

    const int tid  = threadIdx.x;
    const int w    = tid >> 5;
    const int lane = tid & 31;
    const int g    = lane >> 2;
    const int tg   = lane & 3;
    const int m0   = w * 16;
    const int qb   = blockIdx.x * 64;
    const int h    = blockIdx.y;
    const int bb   = blockIdx.z;

    const float* Qbase = Q  + (size_t)bb * Tq * D_MODEL + h * DHEAD;
    const float* Kbase = Kg + (size_t)bb * Tk * D_MODEL + h * DHEAD;
    const float* Vbase = Vg + (size_t)bb * Tk * D_MODEL + h * DHEAD;

    // load Q tile (pre-scaled by 1/sqrt(64)), tf32-converted
#pragma unroll
    for (int i = 0; i < 8; i++) {
        const int f = tid + i * 128;
        const int r = f >> 4, d4 = f & 15;
        float4 v = *(const float4*)(Qbase + (size_t)(qb + r) * D_MODEL + d4 * 4);
        uint4 u = make_uint4(f2tf32(v.x * 0.125f), f2tf32(v.y * 0.125f),
                             f2tf32(v.z * 0.125f), f2tf32(v.w * 0.125f));
        *(uint4*)&Qs[r * QST + d4 * 4] = u;
    }

    float o[8][4];
#pragma unroll
    for (int nt = 0; nt < 8; nt++)
#pragma unroll
        for (int c = 0; c < 4; c++) o[nt][c] = 0.f;
    float mrow0 = -INFINITY, mrow1 = -INFINITY;
    float lrow0 = 0.f, lrow1 = 0.f;

    const int ntiles = causal ? (blockIdx.x + 1) : (Tk >> 6);
    for (int t = 0; t < ntiles; t++) {
        const int kb = t * 64;
        __syncthreads();
#pragma unroll
        for (int i = 0; i < 8; i++) {
            const int f = tid + i * 128;
            const int r = f >> 4, d4 = f & 15;
            float4 kv = *(const float4*)(Kbase + (size_t)(kb + r) * D_MODEL + d4 * 4);
            *(uint4*)&Ks[r * QST + d4 * 4] =
                make_uint4(f2tf32(kv.x), f2tf32(kv.y), f2tf32(kv.z), f2tf32(kv.w));
            float4 vv = *(const float4*)(Vbase + (size_t)(kb + r) * D_MODEL + d4 * 4);
            *(uint4*)&Vs[r * VST + d4 * 4] =
                make_uint4(f2tf32(vv.x), f2tf32(vv.y), f2tf32(vv.z), f2tf32(vv.w));
        }
        __syncthreads();

        // ---- S = Q @ K^T (16x64 per warp) ----
        float s[8][4];
#pragma unroll
        for (int nt = 0; nt < 8; nt++)
#pragma unroll
            for (int c = 0; c < 4; c++) s[nt][c] = 0.f;
#pragma unroll
        for (int kk = 0; kk < 8; kk++) {
            const int k0 = kk * 8;
            const uint32_t a0 = Qs[(m0 + g)     * QST + k0 + tg];
            const uint32_t a1 = Qs[(m0 + g + 8) * QST + k0 + tg];
            const uint32_t a2 = Qs[(m0 + g)     * QST + k0 + tg + 4];
            const uint32_t a3 = Qs[(m0 + g + 8) * QST + k0 + tg + 4];
#pragma unroll
            for (int nt = 0; nt < 8; nt++) {
                const uint32_t b0 = Ks[(nt * 8 + g) * QST + k0 + tg];
                const uint32_t b1 = Ks[(nt * 8 + g) * QST + k0 + tg + 4];
                mma_tf32(s[nt], a0, a1, a2, a3, b0, b1);
            }
        }

        // causal mask (only the diagonal tile needs it)
        if (causal && t == ntiles - 1) {
            const int row0 = qb + m0 + g;
            const int row1 = row0 + 8;
#pragma unroll
            for (int nt = 0; nt < 8; nt++) {
                const int col = kb + nt * 8 + 2 * tg;
                if (col     > row0) s[nt][0] = -1e30f;
                if (col + 1 > row0) s[nt][1] = -1e30f;
                if (col     > row1) s[nt][2] = -1e30f;
                if (col + 1 > row1) s[nt][3] = -1e30f;
            }
        }

        // ---- online softmax (rows g and g+8; quad reduction over tg) ----
        float ml0 = -INFINITY, ml1 = -INFINITY;
#pragma unroll
        for (int nt = 0; nt < 8; nt++) {
            ml0 = fmaxf(ml0, fmaxf(s[nt][0], s[nt][1]));
            ml1 = fmaxf(ml1, fmaxf(s[nt][2], s[nt][3]));
        }
        ml0 = fmaxf(ml0, __shfl_xor_sync(0xffffffffu, ml0, 1));
        ml0 = fmaxf(ml0, __shfl_xor_sync(0xffffffffu, ml0, 2));
        ml1 = fmaxf(ml1, __shfl_xor_sync(0xffffffffu, ml1, 1));
        ml1 = fmaxf(ml1, __shfl_xor_sync(0xffffffffu, ml1, 2));

        const float mn0 = fmaxf(mrow0, ml0);
        const float mn1 = fmaxf(mrow1, ml1);
        const float al0 = __expf(mrow0 - mn0);
        const float al1 = __expf(mrow1 - mn1);
        float ps0 = 0.f, ps1 = 0.f;
#pragma unroll
        for (int nt = 0; nt < 8; nt++) {
            s[nt][0] = __expf(s[nt][0] - mn0);
            s[nt][1] = __expf(s[nt][1] - mn0);
            s[nt][2] = __expf(s[nt][2] - mn1);
            s[nt][3] = __expf(s[nt][3] - mn1);
            ps0 += s[nt][0] + s[nt][1];
            ps1 += s[nt][2] + s[nt][3];
        }
        ps0 += __shfl_xor_sync(0xffffffffu, ps0, 1);
        ps0 += __shfl_xor_sync(0xffffffffu, ps0, 2);
        ps1 += __shfl_xor_sync(0xffffffffu, ps1, 1);
        ps1 += __shfl_xor_sync(0xffffffffu, ps1, 2);
        lrow0 = lrow0 * al0 + ps0;
        lrow1 = lrow1 * al1 + ps1;
        mrow0 = mn0;
        mrow1 = mn1;
#pragma unroll
        for (int nt = 0; nt < 8; nt++) {
            o[nt][0] *= al0; o[nt][1] *= al0;
            o[nt][2] *= al1; o[nt][3] *= al1;
        }

        // ---- write P (tf32) into this warp's private Ps strip ----
#pragma unroll
        for (int nt = 0; nt < 8; nt++) {
            uint2 w0 = make_uint2(f2tf32(s[nt][0]), f2tf32(s[nt][1]));
            uint2 w1 = make_uint2(f2tf32(s[nt][2]), f2tf32(s[nt][3]));
            *(uint2*)&Ps[(m0 + g)     * QST + nt * 8 + 2 * tg] = w0;
            *(uint2*)&Ps[(m0 + g + 8) * QST + nt * 8 + 2 * tg] = w1;
        }
        __syncwarp();

        // ---- O += P @ V ----
#pragma unroll
        for (int kk = 0; kk < 8; kk++) {
            const int k0 = kk * 8;
            const uint32_t a0 = Ps[(m0 + g)     * QST + k0 + tg];
            const uint32_t a1 = Ps[(m0 + g + 8) * QST + k0 + tg];
            const uint32_t a2 = Ps[(m0 + g)     * QST + k0 + tg + 4];
            const uint32_t a3 = Ps[(m0 + g + 8) * QST + k0 + tg + 4];
#pragma unroll
            for (int nt = 0; nt < 8; nt++) {
                const uint32_t b0 = Vs[(k0 + tg)     * VST + nt * 8 + g];
                const uint32_t b1 = Vs[(k0 + tg + 4) * VST + nt * 8 + g];
                mma_tf32(o[nt], a0, a1, a2, a3, b0, b1);
            }
        }
        __syncwarp();   // Ps reads done before next iteration's writes
    }

    // ---- epilogue ----
    const float inv0 = 1.f / lrow0;
    const float inv1 = 1.f / lrow1;
    const int row0 = qb + m0 + g;
    const int row1 = row0 + 8;
#pragma unroll
    for (int nt = 0; nt < 8; nt++) {
        const int col = h * DHEAD + nt * 8 + 2 * tg;
        *(float2*)(O + ((size_t)bb * Tq + row0) * D_MODEL + col) =
            make_float2(o[nt][0] * inv0, o[nt][1] * inv0);
        *(float2*)(O + ((size_t)bb * Tq + row1) * D_MODEL + col) =
            make_float2(o[nt][2] * inv1, o[nt][3] * inv1);
    }
}

// ---------------- LN over rows of 1024 ----------------
__global__ __launch_bounds__(256) void ln_kernel(
    const float* __restrict__ in, const float* __restrict__ g,
    const float* __restrict__ b, float* __restrict__ out)
{
    const int row = blockIdx.x;
    const int tid = threadIdx.x;
    float4 v = ((const float4*)(in + (size_t)row * D_MODEL))[tid];
    float s  = v.x + v.y + v.z + v.w;
    float ss = v.x*v.x + v.y*v.y + v.z*v.z + v.w*v.w;
#pragma unroll
    for (int off = 16; off > 0; off >>= 1) {
        s  += __shfl_xor_sync(0xffffffffu, s,  off);
        ss += __shfl_xor_sync(0xffffffffu, ss, off);
    }
    __shared__ float ws[8], wss[8];
    __shared__ float s_mu, s_inv;
    const int warp = tid >> 5, lane = tid & 31;
    if (lane == 0) { ws[warp] = s; wss[warp] = ss; }
    __syncthreads();
    if (tid == 0) {
        float ts = 0.f, tss = 0.f;
#pragma unroll
        for (int w = 0; w < 8; w++) { ts += ws[w]; tss += wss[w]; }
        float mu = ts * (1.f / D_MODEL);
        float var = tss * (1.f / D_MODEL) - mu * mu;
        s_mu = mu;
        s_inv = rsqrtf(var + 1e-5f);
    }
    __syncthreads();
    float mu = s_mu, inv = s_inv;
    float4 gg = ((const float4*)g)[tid];
    float4 bb = ((const float4*)b)[tid];
    float4 r;
    r.x = (v.x - mu) * inv * gg.x + bb.x;
    r.y = (v.y - mu) * inv * gg.y + bb.y;
    r.z = (v.z - mu) * inv * gg.z + bb.z;
    r.w = (v.w - mu) * inv * gg.w + bb.w;
    ((float4*)(out + (size_t)row * D_MODEL))[tid] = r;
}

// ---------------- orchestration ----------------
extern "C" void kernel_launch(void* const* d_in, const int* in_sizes, int n_in,
                              void* d_out, int out_size)
{
    const float* x     = (const float*)d_in[0];
    const float* enc   = (const float*)d_in[1];
    const float* sa_Wq = (const float*)d_in[4];
    const float* sa_bq = (const float*)d_in[5];
    const float* sa_Wk = (const float*)d_in[6];
    const float* sa_bk = (const float*)d_in[7];
    const float* sa_Wv = (const float*)d_in[8];
    const float* sa_bv = (const float*)d_in[9];
    const float* sa_Wo = (const float*)d_in[10];
    const float* sa_bo = (const float*)d_in[11];
    const float* ca_Wq = (const float*)d_in[12];
    const float* ca_bq = (const float*)d_in[13];
    const float* ca_Wk = (const float*)d_in[14];
    const float* ca_bk = (const float*)d_in[15];
    const float* ca_Wv = (const float*)d_in[16];
    const float* ca_bv = (const float*)d_in[17];
    const float* ca_Wo = (const float*)d_in[18];
    const float* ca_bo = (const float*)d_in[19];
    const float* ff_W1 = (const float*)d_in[20];
    const float* ff_b1 = (const float*)d_in[21];
    const float* ff_W2 = (const float*)d_in[22];
    const float* ff_b2 = (const float*)d_in[23];
    const float* ln1_g = (const float*)d_in[24];
    const float* ln1_b = (const float*)d_in[25];
    const float* ln2_g = (const float*)d_in[26];
    const float* ln2_b = (const float*)d_in[27];
    const float* ln3_g = (const float*)d_in[28];
    const float* ln3_b = (const float*)d_in[29];

    float *q, *k, *v, *ctx, *tmp, *x1, *x2, *ffh;
    cudaGetSymbolAddress((void**)&q,   g_q);
    cudaGetSymbolAddress((void**)&k,   g_k);
    cudaGetSymbolAddress((void**)&v,   g_v);
    cudaGetSymbolAddress((void**)&ctx, g_ctx);
    cudaGetSymbolAddress((void**)&tmp, g_tmp);
    cudaGetSymbolAddress((void**)&x1,  g_x1);
    cudaGetSymbolAddress((void**)&x2,  g_x2);
    cudaGetSymbolAddress((void**)&ffh, g_ffh);

    cudaFuncSetAttribute(flash_attn_mma, cudaFuncAttributeMaxDynamicSharedMemorySize, FA2_SMEM_BYTES);

    dim3 gp(D_MODEL/128, MROWS/128);        // (8, 32) projection GEMMs
    dim3 gf1(DFF_/128,  MROWS/128);         // (32, 32) FFN up
    dim3 gfa(TT/64, NHEAD, BB);             // flash attention

    // --- self attention ---
    gemm_tf32<<<gp, 256>>>(x, sa_Wq, sa_bq, nullptr, q, MROWS, D_MODEL, D_MODEL, 0);
    gemm_tf32<<<gp, 256>>>(x, sa_Wk, sa_bk, nullptr, k, MROWS, D_MODEL, D_MODEL, 0);
    gemm_tf32<<<gp, 256>>>(x, sa_Wv, sa_bv, nullptr, v, MROWS, D_MODEL, D_MODEL, 0);
    flash_attn_mma<<<gfa, 128, FA2_SMEM_BYTES>>>(q, k, v, ctx, TT, TT, 1);
    gemm_tf32<<<gp, 256>>>(ctx, sa_Wo, sa_bo, x, tmp, MROWS, D_MODEL, D_MODEL, 0);
    ln_kernel<<<MROWS, 256>>>(tmp, ln1_g, ln1_b, x1);

    // --- cross attention ---
    gemm_tf32<<<gp, 256>>>(x1,  ca_Wq, ca_bq, nullptr, q, MROWS, D_MODEL, D_MODEL, 0);
    gemm_tf32<<<gp, 256>>>(enc, ca_Wk, ca_bk, nullptr, k, MROWS, D_MODEL, D_MODEL, 0);
    gemm_tf32<<<gp, 256>>>(enc, ca_Wv, ca_bv, nullptr, v, MROWS, D_MODEL, D_MODEL, 0);
    flash_attn_mma<<<gfa, 128, FA2_SMEM_BYTES>>>(q, k, v, ctx, TT, SSEQ, 0);
    gemm_tf32<<<gp, 256>>>(ctx, ca_Wo, ca_bo, x1, tmp, MROWS, D_MODEL, D_MODEL, 0);
    ln_kernel<<<MROWS, 256>>>(tmp, ln2_g, ln2_b, x2);

    // --- FFN ---
    gemm_tf32<<<gf1, 256>>>(x2,  ff_W1, ff_b1, nullptr, ffh, MROWS, DFF_,    D_MODEL, 1);
    gemm_tf32<<<gp, 256>>>(ffh, ff_W2, ff_b2, x2,      tmp, MROWS, D_MODEL, DFF_,    0);
    ln_kernel<<<MROWS, 256>>>(tmp, ln3_g, ln3_b, (float*)d_out);
}

// round 5
// speedup vs baseline: 3.6264x; 1.6305x over previous
#include <cuda_runtime.h>
#include <math.h>
#include <stdint.h>

#define D_MODEL 1024
#define NHEAD   16
#define DHEAD   64
#define BB      2
#define TT      2048
#define SSEQ    2048
#define MROWS   (BB*TT)      // 4096
#define DFF_    4096

// ---------------- scratch (device globals; no runtime allocation) ----------------
__device__ float g_q  [MROWS * D_MODEL];
__device__ float g_k  [MROWS * D_MODEL];
__device__ float g_v  [MROWS * D_MODEL];
__device__ float g_ctx[MROWS * D_MODEL];
__device__ float g_tmp[MROWS * D_MODEL];
__device__ float g_x1 [MROWS * D_MODEL];
__device__ float g_x2 [MROWS * D_MODEL];
__device__ float g_ffh[(size_t)MROWS * DFF_];

__device__ __forceinline__ void mma_tf32(
    float* c, uint32_t a0, uint32_t a1, uint32_t a2, uint32_t a3,
    uint32_t b0, uint32_t b1)
{
    asm volatile(
        "mma.sync.aligned.m16n8k8.row.col.f32.tf32.tf32.f32 "
        "{%0,%1,%2,%3}, {%4,%5,%6,%7}, {%8,%9}, {%0,%1,%2,%3};"
        : "+f"(c[0]), "+f"(c[1]), "+f"(c[2]), "+f"(c[3])
        : "r"(a0), "r"(a1), "r"(a2), "r"(a3), "r"(b0), "r"(b1));
}

__device__ __forceinline__ void cp16(void* smem_ptr, const void* gptr) {
    uint32_t sa = (uint32_t)__cvta_generic_to_shared(smem_ptr);
    asm volatile("cp.async.cg.shared.global [%0], [%1], 16;" :: "r"(sa), "l"(gptr));
}
#define CP_COMMIT() asm volatile("cp.async.commit_group;")
#define CP_WAIT(n)  asm volatile("cp.async.wait_group %0;" :: "n"(n))

// ================= TF32 tensor-core GEMM core (cp.async 4-stage pipeline)
// C = A(MxK) @ B(NxK)^T + bias [+resid][relu]; 128x128 tile, BK=16, 256 thr, 8 warps.
#define AST 20       // smem row stride in floats: 80B/row -> 16B-aligned, bank-clean frags
#define NSTAGE 4

__device__ __forceinline__ void gemm_body(
    const float* __restrict__ A, const float* __restrict__ B,
    const float* __restrict__ bias, const float* __restrict__ resid,
    float* __restrict__ C, int N, int K, int do_relu, int bm, int bn)
{
    __shared__ float As[NSTAGE][128 * AST];
    __shared__ float Bs[NSTAGE][128 * AST];

    const int tid  = threadIdx.x;
    const int warp = tid >> 5;
    const int lane = tid & 31;
    const int g    = lane >> 2;
    const int tg   = lane & 3;
    const int warp_m = (warp & 1) * 64;
    const int warp_n = (warp >> 1) * 32;

    const int r0 = tid >> 2;
    const int c4 = tid & 3;
    const float* Ar0 = A + (size_t)(bm + r0)      * K + c4 * 4;
    const float* Ar1 = A + (size_t)(bm + r0 + 64) * K + c4 * 4;
    const float* Br0 = B + (size_t)(bn + r0)      * K + c4 * 4;
    const float* Br1 = B + (size_t)(bn + r0 + 64) * K + c4 * 4;
    const int soff = r0 * AST + c4 * 4;

    float acc[4][4][4];
#pragma unroll
    for (int i = 0; i < 4; i++)
#pragma unroll
        for (int j = 0; j < 4; j++)
#pragma unroll
            for (int c = 0; c < 4; c++) acc[i][j][c] = 0.f;

    const int nk = K >> 4;

#pragma unroll
    for (int s = 0; s < NSTAGE - 1; s++) {
        const int k0 = s << 4;
        cp16(&As[s][soff],            Ar0 + k0);
        cp16(&As[s][soff + 64 * AST], Ar1 + k0);
        cp16(&Bs[s][soff],            Br0 + k0);
        cp16(&Bs[s][soff + 64 * AST], Br1 + k0);
        CP_COMMIT();
    }

    for (int kt = 0; kt < nk; kt++) {
        CP_WAIT(NSTAGE - 2);
        __syncthreads();

        if (kt + NSTAGE - 1 < nk) {
            const int buf = (kt + NSTAGE - 1) & (NSTAGE - 1);
            const int k0 = (kt + NSTAGE - 1) << 4;
            cp16(&As[buf][soff],            Ar0 + k0);
            cp16(&As[buf][soff + 64 * AST], Ar1 + k0);
            cp16(&Bs[buf][soff],            Br0 + k0);
            cp16(&Bs[buf][soff + 64 * AST], Br1 + k0);
        }
        CP_COMMIT();

        const uint32_t* Ab = (const uint32_t*)As[kt & (NSTAGE - 1)];
        const uint32_t* Bb = (const uint32_t*)Bs[kt & (NSTAGE - 1)];
#pragma unroll
        for (int ks = 0; ks < 2; ks++) {
            const int k0 = ks * 8;
            uint32_t af[4][4], bf[4][2];
#pragma unroll
            for (int i = 0; i < 4; i++) {
                const int row = warp_m + i * 16 + g;
                af[i][0] = Ab[row * AST + k0 + tg];
                af[i][1] = Ab[(row + 8) * AST + k0 + tg];
                af[i][2] = Ab[row * AST + k0 + tg + 4];
                af[i][3] = Ab[(row + 8) * AST + k0 + tg + 4];
            }
#pragma unroll
            for (int j = 0; j < 4; j++) {
                const int col = warp_n + j * 8 + g;
                bf[j][0] = Bb[col * AST + k0 + tg];
                bf[j][1] = Bb[col * AST + k0 + tg + 4];
            }
#pragma unroll
            for (int i = 0; i < 4; i++)
#pragma unroll
                for (int j = 0; j < 4; j++)
                    mma_tf32(acc[i][j], af[i][0], af[i][1], af[i][2], af[i][3],
                             bf[j][0], bf[j][1]);
        }
        __syncthreads();
    }

#pragma unroll
    for (int j = 0; j < 4; j++) {
        const int col = bn + warp_n + j * 8 + tg * 2;
        const float bx = bias[col], by = bias[col + 1];
#pragma unroll
        for (int i = 0; i < 4; i++) {
            const int row0 = bm + warp_m + i * 16 + g;
            const int row1 = row0 + 8;
            float o00 = acc[i][j][0] + bx, o01 = acc[i][j][1] + by;
            float o10 = acc[i][j][2] + bx, o11 = acc[i][j][3] + by;
            if (do_relu) {
                o00 = fmaxf(o00, 0.f); o01 = fmaxf(o01, 0.f);
                o10 = fmaxf(o10, 0.f); o11 = fmaxf(o11, 0.f);
            }
            if (resid) {
                const float2 r0v = *(const float2*)(resid + (size_t)row0 * N + col);
                const float2 r1v = *(const float2*)(resid + (size_t)row1 * N + col);
                o00 += r0v.x; o01 += r0v.y; o10 += r1v.x; o11 += r1v.y;
            }
            *(float2*)(C + (size_t)row0 * N + col) = make_float2(o00, o01);
            *(float2*)(C + (size_t)row1 * N + col) = make_float2(o10, o11);
        }
    }
}

__global__ __launch_bounds__(256) void gemm_tf32(
    const float* __restrict__ A, const float* __restrict__ B,
    const float* __restrict__ bias, const float* __restrict__ resid,
    float* __restrict__ C, int N, int K, int do_relu)
{
    gemm_body(A, B, bias, resid, C, N, K, do_relu,
              blockIdx.y * 128, blockIdx.x * 128);
}

// multi-weight projection: grid.x = nw*8; weight/bias/output selected per block.
__global__ __launch_bounds__(256) void gemm_tf32_multi(
    const float* __restrict__ A,
    const float* __restrict__ W0, const float* __restrict__ W1, const float* __restrict__ W2,
    const float* __restrict__ b0, const float* __restrict__ b1, const float* __restrict__ b2,
    float* __restrict__ C0, float* __restrict__ C1, float* __restrict__ C2)
{
    const int wsel = blockIdx.x >> 3;
    const int bn = (blockIdx.x & 7) * 128;
    const float* B    = (wsel == 0) ? W0 : (wsel == 1) ? W1 : W2;
    const float* bias = (wsel == 0) ? b0 : (wsel == 1) ? b1 : b2;
    float* C          = (wsel == 0) ? C0 : (wsel == 1) ? C1 : C2;
    gemm_body(A, B, bias, nullptr, C, D_MODEL, D_MODEL, 0,
              blockIdx.y * 128, bn);
}

// ================= Flash attention with TF32 mma. Br=Bc=64, 128 threads (4 warps).
#define QST 68   // 68 % 32 == 4 -> 4g+tg conflict-free
#define VST 72   // 72 % 32 == 8 -> 8tg+g conflict-free
#define FA2_SMEM_U32 (64*QST*3 + 64*VST)
#define FA2_SMEM_BYTES (FA2_SMEM_U32 * 4)

__global__ __launch_bounds__(128) void flash_attn_mma(
    const float* __restrict__ Q, const float* __restrict__ Kg,
    const float* __restrict__ Vg, float* __restrict__ O,
    int Tq, int Tk, int causal)
{
    extern __shared__ uint32_t smu[];
    uint32_t* Qs = smu;
    uint32_t* Ks = smu + 64 * QST;
    uint32_t* Ps = smu + 2 * 64 * QST;
    uint32_t* Vs = smu + 3 * 64 * QST;

    const int tid  = threadIdx.x;
    const int w    = tid >> 5;
    const int lane = tid & 31;
    const int g    = lane >> 2;
    const int tg   = lane & 3;
    const int m0   = w * 16;
    // causal: launch heaviest tiles first (reverse index) for better tail packing
    const int qtile = causal ? ((int)gridDim.x - 1 - (int)blockIdx.x) : (int)blockIdx.x;
    const int qb   = qtile * 64;
    const int h    = blockIdx.y;
    const int bb   = blockIdx.z;

    const float* Qbase = Q  + (size_t)bb * Tq * D_MODEL + h * DHEAD;
    const float* Kbase = Kg + (size_t)bb * Tk * D_MODEL + h * DHEAD;
    const float* Vbase = Vg + (size_t)bb * Tk * D_MODEL + h * DHEAD;

#pragma unroll
    for (int i = 0; i < 8; i++) {
        const int f = tid + i * 128;
        const int r = f >> 4, d4 = f & 15;
        float4 v = *(const float4*)(Qbase + (size_t)(qb + r) * D_MODEL + d4 * 4);
        uint4 u = make_uint4(__float_as_uint(v.x * 0.125f), __float_as_uint(v.y * 0.125f),
                             __float_as_uint(v.z * 0.125f), __float_as_uint(v.w * 0.125f));
        *(uint4*)&Qs[r * QST + d4 * 4] = u;
    }

    float o[8][4];
#pragma unroll
    for (int nt = 0; nt < 8; nt++)
#pragma unroll
        for (int c = 0; c < 4; c++) o[nt][c] = 0.f;
    float mrow0 = -INFINITY, mrow1 = -INFINITY;
    float lrow0 = 0.f, lrow1 = 0.f;

    const int ntiles = causal ? (qtile + 1) : (Tk >> 6);
    for (int t = 0; t < ntiles; t++) {
        const int kb = t * 64;
        __syncthreads();
#pragma unroll
        for (int i = 0; i < 8; i++) {
            const int f = tid + i * 128;
            const int r = f >> 4, d4 = f & 15;
            *(uint4*)&Ks[r * QST + d4 * 4] =
                *(const uint4*)(Kbase + (size_t)(kb + r) * D_MODEL + d4 * 4);
            *(uint4*)&Vs[r * VST + d4 * 4] =
                *(const uint4*)(Vbase + (size_t)(kb + r) * D_MODEL + d4 * 4);
        }
        __syncthreads();

        // ---- S = Q @ K^T (16x64 per warp) ----
        float s[8][4];
#pragma unroll
        for (int nt = 0; nt < 8; nt++)
#pragma unroll
            for (int c = 0; c < 4; c++) s[nt][c] = 0.f;
#pragma unroll
        for (int kk = 0; kk < 8; kk++) {
            const int k0 = kk * 8;
            const uint32_t a0 = Qs[(m0 + g)     * QST + k0 + tg];
            const uint32_t a1 = Qs[(m0 + g + 8) * QST + k0 + tg];
            const uint32_t a2 = Qs[(m0 + g)     * QST + k0 + tg + 4];
            const uint32_t a3 = Qs[(m0 + g + 8) * QST + k0 + tg + 4];
#pragma unroll
            for (int nt = 0; nt < 8; nt++) {
                const uint32_t b0 = Ks[(nt * 8 + g) * QST + k0 + tg];
                const uint32_t b1 = Ks[(nt * 8 + g) * QST + k0 + tg + 4];
                mma_tf32(s[nt], a0, a1, a2, a3, b0, b1);
            }
        }

        if (causal && t == ntiles - 1) {
            const int row0 = qb + m0 + g;
            const int row1 = row0 + 8;
#pragma unroll
            for (int nt = 0; nt < 8; nt++) {
                const int col = kb + nt * 8 + 2 * tg;
                if (col     > row0) s[nt][0] = -1e30f;
                if (col + 1 > row0) s[nt][1] = -1e30f;
                if (col     > row1) s[nt][2] = -1e30f;
                if (col + 1 > row1) s[nt][3] = -1e30f;
            }
        }

        // ---- online softmax ----
        float ml0 = -INFINITY, ml1 = -INFINITY;
#pragma unroll
        for (int nt = 0; nt < 8; nt++) {
            ml0 = fmaxf(ml0, fmaxf(s[nt][0], s[nt][1]));
            ml1 = fmaxf(ml1, fmaxf(s[nt][2], s[nt][3]));
        }
        ml0 = fmaxf(ml0, __shfl_xor_sync(0xffffffffu, ml0, 1));
        ml0 = fmaxf(ml0, __shfl_xor_sync(0xffffffffu, ml0, 2));
        ml1 = fmaxf(ml1, __shfl_xor_sync(0xffffffffu, ml1, 1));
        ml1 = fmaxf(ml1, __shfl_xor_sync(0xffffffffu, ml1, 2));

        const float mn0 = fmaxf(mrow0, ml0);
        const float mn1 = fmaxf(mrow1, ml1);
        const float al0 = __expf(mrow0 - mn0);
        const float al1 = __expf(mrow1 - mn1);
        float ps0 = 0.f, ps1 = 0.f;
#pragma unroll
        for (int nt = 0; nt < 8; nt++) {
            s[nt][0] = __expf(s[nt][0] - mn0);
            s[nt][1] = __expf(s[nt][1] - mn0);
            s[nt][2] = __expf(s[nt][2] - mn1);
            s[nt][3] = __expf(s[nt][3] - mn1);
            ps0 += s[nt][0] + s[nt][1];
            ps1 += s[nt][2] + s[nt][3];
        }
        ps0 += __shfl_xor_sync(0xffffffffu, ps0, 1);
        ps0 += __shfl_xor_sync(0xffffffffu, ps0, 2);
        ps1 += __shfl_xor_sync(0xffffffffu, ps1, 1);
        ps1 += __shfl_xor_sync(0xffffffffu, ps1, 2);
        lrow0 = lrow0 * al0 + ps0;
        lrow1 = lrow1 * al1 + ps1;
        mrow0 = mn0;
        mrow1 = mn1;
#pragma unroll
        for (int nt = 0; nt < 8; nt++) {
            o[nt][0] *= al0; o[nt][1] *= al0;
            o[nt][2] *= al1; o[nt][3] *= al1;
        }

        // ---- P -> warp-private smem strip (raw fp32 bits) ----
#pragma unroll
        for (int nt = 0; nt < 8; nt++) {
            uint2 w0 = make_uint2(__float_as_uint(s[nt][0]), __float_as_uint(s[nt][1]));
            uint2 w1 = make_uint2(__float_as_uint(s[nt][2]), __float_as_uint(s[nt][3]));
            *(uint2*)&Ps[(m0 + g)     * QST + nt * 8 + 2 * tg] = w0;
            *(uint2*)&Ps[(m0 + g + 8) * QST + nt * 8 + 2 * tg] = w1;
        }
        __syncwarp();

        // ---- O += P @ V ----
#pragma unroll
        for (int kk = 0; kk < 8; kk++) {
            const int k0 = kk * 8;
            const uint32_t a0 = Ps[(m0 + g)     * QST + k0 + tg];
            const uint32_t a1 = Ps[(m0 + g + 8) * QST + k0 + tg];
            const uint32_t a2 = Ps[(m0 + g)     * QST + k0 + tg + 4];
            const uint32_t a3 = Ps[(m0 + g + 8) * QST + k0 + tg + 4];
#pragma unroll
            for (int nt = 0; nt < 8; nt++) {
                const uint32_t b0 = Vs[(k0 + tg)     * VST + nt * 8 + g];
                const uint32_t b1 = Vs[(k0 + tg + 4) * VST + nt * 8 + g];
                mma_tf32(o[nt], a0, a1, a2, a3, b0, b1);
            }
        }
        __syncwarp();
    }

    const float inv0 = 1.f / lrow0;
    const float inv1 = 1.f / lrow1;
    const int row0 = qb + m0 + g;
    const int row1 = row0 + 8;
#pragma unroll
    for (int nt = 0; nt < 8; nt++) {
        const int col = h * DHEAD + nt * 8 + 2 * tg;
        *(float2*)(O + ((size_t)bb * Tq + row0) * D_MODEL + col) =
            make_float2(o[nt][0] * inv0, o[nt][1] * inv0);
        *(float2*)(O + ((size_t)bb * Tq + row1) * D_MODEL + col) =
            make_float2(o[nt][2] * inv1, o[nt][3] * inv1);
    }
}

// ---------------- LN over rows of 1024 ----------------
__global__ __launch_bounds__(256) void ln_kernel(
    const float* __restrict__ in, const float* __restrict__ g,
    const float* __restrict__ b, float* __restrict__ out)
{
    const int row = blockIdx.x;
    const int tid = threadIdx.x;
    float4 v = ((const float4*)(in + (size_t)row * D_MODEL))[tid];
    float s  = v.x + v.y + v.z + v.w;
    float ss = v.x*v.x + v.y*v.y + v.z*v.z + v.w*v.w;
#pragma unroll
    for (int off = 16; off > 0; off >>= 1) {
        s  += __shfl_xor_sync(0xffffffffu, s,  off);
        ss += __shfl_xor_sync(0xffffffffu, ss, off);
    }
    __shared__ float ws[8], wss[8];
    __shared__ float s_mu, s_inv;
    const int warp = tid >> 5, lane = tid & 31;
    if (lane == 0) { ws[warp] = s; wss[warp] = ss; }
    __syncthreads();
    if (tid == 0) {
        float ts = 0.f, tss = 0.f;
#pragma unroll
        for (int w = 0; w < 8; w++) { ts += ws[w]; tss += wss[w]; }
        float mu = ts * (1.f / D_MODEL);
        float var = tss * (1.f / D_MODEL) - mu * mu;
        s_mu = mu;
        s_inv = rsqrtf(var + 1e-5f);
    }
    __syncthreads();
    float mu = s_mu, inv = s_inv;
    float4 gg = ((const float4*)g)[tid];
    float4 bb = ((const float4*)b)[tid];
    float4 r;
    r.x = (v.x - mu) * inv * gg.x + bb.x;
    r.y = (v.y - mu) * inv * gg.y + bb.y;
    r.z = (v.z - mu) * inv * gg.z + bb.z;
    r.w = (v.w - mu) * inv * gg.w + bb.w;
    ((float4*)(out + (size_t)row * D_MODEL))[tid] = r;
}

// ---------------- orchestration ----------------
extern "C" void kernel_launch(void* const* d_in, const int* in_sizes, int n_in,
                              void* d_out, int out_size)
{
    const float* x     = (const float*)d_in[0];
    const float* enc   = (const float*)d_in[1];
    const float* sa_Wq = (const float*)d_in[4];
    const float* sa_bq = (const float*)d_in[5];
    const float* sa_Wk = (const float*)d_in[6];
    const float* sa_bk = (const float*)d_in[7];
    const float* sa_Wv = (const float*)d_in[8];
    const float* sa_bv = (const float*)d_in[9];
    const float* sa_Wo = (const float*)d_in[10];
    const float* sa_bo = (const float*)d_in[11];
    const float* ca_Wq = (const float*)d_in[12];
    const float* ca_bq = (const float*)d_in[13];
    const float* ca_Wk = (const float*)d_in[14];
    const float* ca_bk = (const float*)d_in[15];
    const float* ca_Wv = (const float*)d_in[16];
    const float* ca_bv = (const float*)d_in[17];
    const float* ca_Wo = (const float*)d_in[18];
    const float* ca_bo = (const float*)d_in[19];
    const float* ff_W1 = (const float*)d_in[20];
    const float* ff_b1 = (const float*)d_in[21];
    const float* ff_W2 = (const float*)d_in[22];
    const float* ff_b2 = (const float*)d_in[23];
    const float* ln1_g = (const float*)d_in[24];
    const float* ln1_b = (const float*)d_in[25];
    const float* ln2_g = (const float*)d_in[26];
    const float* ln2_b = (const float*)d_in[27];
    const float* ln3_g = (const float*)d_in[28];
    const float* ln3_b = (const float*)d_in[29];

    float *q, *k, *v, *ctx, *tmp, *x1, *x2, *ffh;
    cudaGetSymbolAddress((void**)&q,   g_q);
    cudaGetSymbolAddress((void**)&k,   g_k);
    cudaGetSymbolAddress((void**)&v,   g_v);
    cudaGetSymbolAddress((void**)&ctx, g_ctx);
    cudaGetSymbolAddress((void**)&tmp, g_tmp);
    cudaGetSymbolAddress((void**)&x1,  g_x1);
    cudaGetSymbolAddress((void**)&x2,  g_x2);
    cudaGetSymbolAddress((void**)&ffh, g_ffh);

    cudaFuncSetAttribute(flash_attn_mma, cudaFuncAttributeMaxDynamicSharedMemorySize, FA2_SMEM_BYTES);

    dim3 gqkv(24, MROWS/128);               // fused q,k,v projections
    dim3 gkv2(16, MROWS/128);               // fused cross k,v
    dim3 gq1(8,  MROWS/128);                // single projection
    dim3 gp(D_MODEL/128, MROWS/128);
    dim3 gf1(DFF_/128,  MROWS/128);
    dim3 gfa(TT/64, NHEAD, BB);

    // --- self attention ---
    gemm_tf32_multi<<<gqkv, 256>>>(x, sa_Wq, sa_Wk, sa_Wv, sa_bq, sa_bk, sa_bv, q, k, v);
    flash_attn_mma<<<gfa, 128, FA2_SMEM_BYTES>>>(q, k, v, ctx, TT, TT, 1);
    gemm_tf32<<<gp, 256>>>(ctx, sa_Wo, sa_bo, x, tmp, D_MODEL, D_MODEL, 0);
    ln_kernel<<<MROWS, 256>>>(tmp, ln1_g, ln1_b, x1);

    // --- cross attention (K/V of enc are independent of x1 -> issue first) ---
    gemm_tf32_multi<<<gkv2, 256>>>(enc, ca_Wk, ca_Wv, nullptr, ca_bk, ca_bv, nullptr, k, v, nullptr);
    gemm_tf32<<<gq1, 256>>>(x1, ca_Wq, ca_bq, nullptr, q, D_MODEL, D_MODEL, 0);
    flash_attn_mma<<<gfa, 128, FA2_SMEM_BYTES>>>(q, k, v, ctx, TT, SSEQ, 0);
    gemm_tf32<<<gp, 256>>>(ctx, ca_Wo, ca_bo, x1, tmp, D_MODEL, D_MODEL, 0);
    ln_kernel<<<MROWS, 256>>>(tmp, ln2_g, ln2_b, x2);

    // --- FFN ---
    gemm_tf32<<<gf1, 256>>>(x2,  ff_W1, ff_b1, nullptr, ffh, DFF_,    D_MODEL, 1);
    gemm_tf32<<<gp, 256>>>(ffh, ff_W2, ff_b2, x2,      tmp, D_MODEL, DFF_,    0);
    ln_kernel<<<MROWS, 256>>>(tmp, ln3_g, ln3_b, (float*)d_out);
}